// round 6
// baseline (speedup 1.0000x reference)
#include <cuda_runtime.h>

// gconv_19301583028599 — adaptive graph conv as fused flash-attention, f32x2 edition.
//
// y = softmax(relu(adj @ adj^T)) @ X      (X = x transposed to [N, B*INP])
// out[b,n,o] = x[b,n,:]·W0[n,:,o] + y[b,n,:]·W1[n,:,o] + bias[n,o]

#define NN   8192
#define BB   32
#define EMB  16
#define TQ   64
#define TK   64

#define QT_PITCH   66
#define KTD_PITCH  132
#define PSD_PITCH  130
#define YS_PITCH   68

// smem layout (float offsets). All vector-load bases 16B-aligned.
#define OFF_QT    0
#define SZ_QT     (EMB * QT_PITCH)          // 1056
#define OFF_PSD   (OFF_QT + SZ_QT)          // 1056  (byte 4224, 16B ok)
#define SZ_PSD    (TQ * PSD_PITCH)          // 8320
#define OFF_KTD   (OFF_PSD + SZ_PSD)        // 9376
#define SZ_KTD    (EMB * KTD_PITCH)         // 2112
#define OFF_VS    (OFF_KTD + SZ_KTD)        // 11488
#define SZ_VS     (TK * 64)                 // 4096
#define SMEM_FLOATS (OFF_VS + SZ_VS)        // 15584 -> 62336 B
// epilogue overlays
#define OFF_YS    OFF_PSD                   // 64*68 = 4352 floats
#define OFF_LRED  (OFF_PSD + 4352)          // 256 floats
#define OFF_WPS   OFF_VS                    // 4096 floats
#define OFF_BPS   OFF_KTD                   // 1024 floats

typedef unsigned long long u64;

__device__ float g_Xt[NN * 64];   // Xt[m][2b+c] = x[b][m][c]

__global__ void transpose_x_kernel(const float* __restrict__ x) {
    int m = blockIdx.x * blockDim.x + threadIdx.x;
    if (m >= NN) return;
    float row[64];
#pragma unroll
    for (int b = 0; b < BB; b++) {
        float2 v = *(const float2*)(x + ((size_t)b * NN + m) * 2);
        row[2 * b] = v.x;  row[2 * b + 1] = v.y;
    }
    float4* dst = (float4*)(g_Xt + (size_t)m * 64);
#pragma unroll
    for (int q = 0; q < 16; q++) dst[q] = ((float4*)row)[q];
}

__device__ __forceinline__ u64 ffma2(u64 a, u64 b, u64 c) {
    u64 d;
    asm("fma.rn.f32x2 %0, %1, %2, %3;" : "=l"(d) : "l"(a), "l"(b), "l"(c));
    return d;
}
__device__ __forceinline__ float2 unpk(u64 v) {
    float2 r;
    asm("mov.b64 {%0, %1}, %2;" : "=f"(r.x), "=f"(r.y) : "l"(v));
    return r;
}

extern __shared__ float smf[];

__global__ __launch_bounds__(512, 1) void gconv_attn_kernel(
    const float* __restrict__ adj,
    const float* __restrict__ wp,
    const float* __restrict__ bp,
    float* __restrict__ out)
{
    float* Qt  = smf + OFF_QT;
    float* Psd = smf + OFF_PSD;
    float* Ktd = smf + OFF_KTD;
    float* Vs  = smf + OFF_VS;

    const int tid = threadIdx.x;
    const int jj = tid & 3;             // 4 col-groups per warp
    const int ii = (tid >> 2) & 7;      // 8 row-pair-groups per warp
    const int w  = tid >> 5;            // warp 0..15
    const int cb = w & 3;               // col-block
    const int rb = w >> 2;              // row-block
    const int J  = cb * 4 + jj;         // global col-group 0..15 (4 cols each)
    const int I  = rb * 8 + ii;         // global row-pair 0..31
    const int row0 = 2 * I;
    const int n0 = blockIdx.x * TQ;

    // Q tile, transposed: Qt[d][r] = adj[n0+r][d]
#pragma unroll
    for (int t = 0; t < 2; t++) {
        int idx = tid + 512 * t;
        int r = idx >> 4, d = idx & 15;
        Qt[d * QT_PITCH + r] = adj[(n0 + r) * EMB + d];
    }

    // prefetch tile 0 into registers
    const int kr0 = tid >> 4, kd = tid & 15;
    const int kr1 = kr0 + 32;
    float ka = adj[kr0 * EMB + kd];
    float kb = adj[kr1 * EMB + kd];
    float4 va = ((const float4*)g_Xt)[tid];
    float4 vb = ((const float4*)g_Xt)[tid + 512];

    u64 a00 = 0, a01 = 0, a10 = 0, a11 = 0;   // acc pairs: (col 4J..4J+3) x (row0,row1)
    float lp0 = 0.f, lp1 = 0.f;               // partial row-sums over this thread's 4 keys

    float* pr0 = Psd + row0 * PSD_PITCH;
    float* pr1 = pr0 + PSD_PITCH;
    const float* vp = Vs + 4 * J;
    const float* qp = Qt + row0;
    const float* kp = Ktd + 8 * J;

    for (int kt = 0; kt < NN; kt += TK) {
        __syncthreads();   // prev PV done: Ktd/Vs/Psd safe to overwrite
        // stage K (duplicated) + V from registers
        *(float2*)&Ktd[kd * KTD_PITCH + 2 * kr0] = make_float2(ka, ka);
        *(float2*)&Ktd[kd * KTD_PITCH + 2 * kr1] = make_float2(kb, kb);
        ((float4*)Vs)[tid]       = va;
        ((float4*)Vs)[tid + 512] = vb;
        __syncthreads();

        // prefetch next tile (latency hidden under score+PV)
        int ktn = kt + TK; if (ktn >= NN) ktn = 0;
        ka = adj[(ktn + kr0) * EMB + kd];
        kb = adj[(ktn + kr1) * EMB + kd];
        va = ((const float4*)(g_Xt + (size_t)ktn * 64))[tid];
        vb = ((const float4*)(g_Xt + (size_t)ktn * 64))[tid + 512];

        // ---- scores, packed across rows: s[c] = (s[row0][4J+c], s[row1][4J+c]) ----
        u64 s0 = 0, s1 = 0, s2v = 0, s3 = 0;
#pragma unroll
        for (int d = 0; d < EMB; d++) {
            u64 q2 = *(const u64*)(qp + d * QT_PITCH);                 // (q_r0, q_r1)
            ulonglong2 kA = *(const ulonglong2*)(kp + d * KTD_PITCH);      // keys 4J,4J+1 dup
            ulonglong2 kB = *(const ulonglong2*)(kp + d * KTD_PITCH + 4);  // keys 4J+2,4J+3 dup
            s0  = ffma2(q2, kA.x, s0);
            s1  = ffma2(q2, kA.y, s1);
            s2v = ffma2(q2, kB.x, s2v);
            s3  = ffma2(q2, kB.y, s3);
        }

        // ---- exp(relu(s)) -> duplicated P store; accumulate partial row sums ----
        {
            float2 ua = unpk(s0), ub = unpk(s1), uc = unpk(s2v), ud = unpk(s3);
            const int c0 = 8 * J;
            float p;
            p = __expf(fminf(fmaxf(ua.x, 0.f), 70.f)); lp0 += p; *(float2*)&pr0[c0]     = make_float2(p, p);
            p = __expf(fminf(fmaxf(ua.y, 0.f), 70.f)); lp1 += p; *(float2*)&pr1[c0]     = make_float2(p, p);
            p = __expf(fminf(fmaxf(ub.x, 0.f), 70.f)); lp0 += p; *(float2*)&pr0[c0 + 2] = make_float2(p, p);
            p = __expf(fminf(fmaxf(ub.y, 0.f), 70.f)); lp1 += p; *(float2*)&pr1[c0 + 2] = make_float2(p, p);
            p = __expf(fminf(fmaxf(uc.x, 0.f), 70.f)); lp0 += p; *(float2*)&pr0[c0 + 4] = make_float2(p, p);
            p = __expf(fminf(fmaxf(uc.y, 0.f), 70.f)); lp1 += p; *(float2*)&pr1[c0 + 4] = make_float2(p, p);
            p = __expf(fminf(fmaxf(ud.x, 0.f), 70.f)); lp0 += p; *(float2*)&pr0[c0 + 6] = make_float2(p, p);
            p = __expf(fminf(fmaxf(ud.y, 0.f), 70.f)); lp1 += p; *(float2*)&pr1[c0 + 6] = make_float2(p, p);
        }
        __syncthreads();   // all P written

        // ---- PV: acc += P(dup pairs) * V(natural pairs) ----
#pragma unroll 8
        for (int kk = 0; kk < TK; kk += 2) {
            ulonglong2 v0 = *(const ulonglong2*)(vp + kk * 64);
            ulonglong2 v1 = *(const ulonglong2*)(vp + kk * 64 + 64);
            u64 pa0 = *(const u64*)(pr0 + 2 * kk);
            u64 pa1 = *(const u64*)(pr0 + 2 * kk + 2);
            u64 pb0 = *(const u64*)(pr1 + 2 * kk);
            u64 pb1 = *(const u64*)(pr1 + 2 * kk + 2);
            a00 = ffma2(pa0, v0.x, a00);  a01 = ffma2(pa0, v0.y, a01);
            a10 = ffma2(pb0, v0.x, a10);  a11 = ffma2(pb0, v0.y, a11);
            a00 = ffma2(pa1, v1.x, a00);  a01 = ffma2(pa1, v1.y, a01);
            a10 = ffma2(pb1, v1.x, a10);  a11 = ffma2(pb1, v1.y, a11);
        }
    }
    __syncthreads();   // mainloop fully done

    // ---- final row-sum reduction: over jj (shfl) then over cb (smem) ----
    lp0 += __shfl_xor_sync(0xffffffffu, lp0, 1);
    lp0 += __shfl_xor_sync(0xffffffffu, lp0, 2);
    lp1 += __shfl_xor_sync(0xffffffffu, lp1, 1);
    lp1 += __shfl_xor_sync(0xffffffffu, lp1, 2);
    float* lred = smf + OFF_LRED;
    if (jj == 0) {
        lred[row0 * 4 + cb]       = lp0;
        lred[(row0 + 1) * 4 + cb] = lp1;
    }
    // stage pools into overlay regions (Vs/Ktd dead)
    float* wpsm = smf + OFF_WPS;
    float* bpsm = smf + OFF_BPS;
    ((float4*)wpsm)[tid]       = ((const float4*)wp)[tid];
    ((float4*)wpsm)[tid + 512] = ((const float4*)wp)[tid + 512];
    if (tid < 256) ((float4*)bpsm)[tid] = ((const float4*)bp)[tid];
    __syncthreads();

    // normalize y, store to Ysm
    float* Ysm = smf + OFF_YS;
    {
        float inv0 = 1.f / (lred[row0 * 4] + lred[row0 * 4 + 1] + lred[row0 * 4 + 2] + lred[row0 * 4 + 3]);
        float inv1 = 1.f / (lred[(row0 + 1) * 4] + lred[(row0 + 1) * 4 + 1] +
                            lred[(row0 + 1) * 4 + 2] + lred[(row0 + 1) * 4 + 3]);
        float2 u00 = unpk(a00), u01 = unpk(a01), u10 = unpk(a10), u11 = unpk(a11);
        *(float4*)&Ysm[row0 * YS_PITCH + 4 * J] =
            make_float4(u00.x * inv0, u00.y * inv0, u01.x * inv0, u01.y * inv0);
        *(float4*)&Ysm[(row0 + 1) * YS_PITCH + 4 * J] =
            make_float4(u10.x * inv1, u10.y * inv1, u11.x * inv1, u11.y * inv1);
    }
    __syncthreads();

    // ---- epilogue: out[b,n,o] = bias + x·W0 + y·W1 ----
    const int o  = tid & 63;
    const int ng = tid >> 6;   // 0..7, 8 rows each
#pragma unroll
    for (int q = 0; q < 8; q++) {
        int n = ng * 8 + q;
        float w00 = 0.f, w01 = 0.f, w10 = 0.f, w11 = 0.f, bbv = 0.f;
#pragma unroll
        for (int d = 0; d < EMB; d++) {
            float a = Qt[d * QT_PITCH + n];
            const float* wrow = wpsm + d * 256 + o;   // wp[d][k][i][o] at (d*4 + 2k + i)*64 + o
            w00 += a * wrow[0];
            w01 += a * wrow[64];
            w10 += a * wrow[128];
            w11 += a * wrow[192];
            bbv += a * bpsm[d * 64 + o];
        }
        int gn = n0 + n;
        const float* xrow = g_Xt + (size_t)gn * 64;
        const float* yrow = Ysm + n * YS_PITCH;
        float* orow = out + (size_t)gn * 64 + o;
#pragma unroll 4
        for (int b = 0; b < BB; b++) {
            float2 xv = *(const float2*)(xrow + 2 * b);
            float2 yv = *(const float2*)(yrow + 2 * b);
            orow[(size_t)b * (NN * 64)] = bbv + xv.x * w00 + xv.y * w01 + yv.x * w10 + yv.y * w11;
        }
    }
}

extern "C" void kernel_launch(void* const* d_in, const int* in_sizes, int n_in,
                              void* d_out, int out_size) {
    const float* x   = (const float*)d_in[0];   // [32, 8192, 2]
    const float* adj = (const float*)d_in[1];   // [8192, 16]
    const float* wp  = (const float*)d_in[2];   // [16, 2, 2, 64]
    const float* bp  = (const float*)d_in[3];   // [16, 64]
    float* out = (float*)d_out;                 // [32, 8192, 64]

    cudaFuncSetAttribute(gconv_attn_kernel,
                         cudaFuncAttributeMaxDynamicSharedMemorySize,
                         SMEM_FLOATS * (int)sizeof(float));
    transpose_x_kernel<<<NN / 256, 256>>>(x);
    gconv_attn_kernel<<<NN / TQ, 512, SMEM_FLOATS * sizeof(float)>>>(adj, wp, bp, out);
}

// round 7
// speedup vs baseline: 1.7980x; 1.7980x over previous
#include <cuda_runtime.h>

// gconv_19301583028599 — adaptive graph conv as fused flash-attention.
// f32x2 edition v2: 4 concurrent key-subtiles, transposed P, swizzled V/K,
// deferred key-reduction. Crossbar traffic engineered below the FFMA2 floor.
//
// y = softmax(relu(adj @ adj^T)) @ X      (X = x transposed to [N, B*INP])
// out[b,n,o] = x[b,n,:]·W0[n,:,o] + y[b,n,:]·W1[n,:,o] + bias[n,o]

#define NN   8192
#define BB   32
#define EMB  16
#define TQ   64
#define NH   4          // concurrent key-subtiles
#define KS   64         // keys per subtile
#define KITER (NH * KS) // 256 keys per iteration
#define ITERS (NN / KITER)

// smem layout (float offsets)
#define OFF_QTD  0                       // Qtd[d][dup 2r]  16 x 132
#define OFF_KT   2112                    // Kt[h][d][64 sw + pad] 4 x 16 x 68
#define OFF_VS   6464                    // Vs[h][k][64 sw] 4 x 64 x 64
#define OFF_PT   22848                   // Pt[h][k][row 70] 4 x 64 x 70
#define OFF_LRED 40768                   // lred[h][64]
#define SMEM_FLOATS 41024                // 164,096 B
// overlays (after mainloop)
#define OFF_YS   OFF_PT                  // 64 x 68
#define OFF_ACC  (OFF_PT + 4480)         // 3 x 128 x 32
#define OFF_WPS  OFF_VS                  // 4096
#define OFF_BPS  (OFF_VS + 4096)         // 1024

typedef unsigned long long u64;

__device__ float g_Xt[NN * 64];   // Xt[m][2b+c] = x[b][m][c]

__global__ void transpose_x_kernel(const float* __restrict__ x) {
    int m = blockIdx.x * blockDim.x + threadIdx.x;
    if (m >= NN) return;
    float row[64];
#pragma unroll
    for (int b = 0; b < BB; b++) {
        float2 v = *(const float2*)(x + ((size_t)b * NN + m) * 2);
        row[2 * b] = v.x;  row[2 * b + 1] = v.y;
    }
    float4* dst = (float4*)(g_Xt + (size_t)m * 64);
#pragma unroll
    for (int q = 0; q < 16; q++) dst[q] = ((float4*)row)[q];
}

__device__ __forceinline__ u64 ffma2(u64 a, u64 b, u64 c) {
    u64 d;
    asm("fma.rn.f32x2 %0, %1, %2, %3;" : "=l"(d) : "l"(a), "l"(b), "l"(c));
    return d;
}
__device__ __forceinline__ u64 add2(u64 a, u64 b) {
    u64 d;
    asm("add.rn.f32x2 %0, %1, %2;" : "=l"(d) : "l"(a), "l"(b));
    return d;
}
__device__ __forceinline__ float2 unpk(u64 v) {
    float2 r;
    asm("mov.b64 {%0, %1}, %2;" : "=f"(r.x), "=f"(r.y) : "l"(v));
    return r;
}
__device__ __forceinline__ u64 pk2(float v) {   // (v, v)
    u64 d;
    asm("mov.b64 %0, {%1, %1};" : "=l"(d) : "f"(v));
    return d;
}

extern __shared__ float smf[];

__global__ __launch_bounds__(512, 1) void gconv_attn_kernel(
    const float* __restrict__ adj,
    const float* __restrict__ wp,
    const float* __restrict__ bp,
    float* __restrict__ out)
{
    float* Qtd = smf + OFF_QTD;
    float* Kt  = smf + OFF_KT;
    float* Vs  = smf + OFF_VS;
    float* Pt  = smf + OFF_PT;
    float* lred = smf + OFF_LRED;

    const int tid  = threadIdx.x;
    const int half = tid >> 7;          // 0..3 key-subtile
    const int t7   = tid & 127;
    const int i4   = t7 >> 3;           // 0..15: rows 4*i4 .. 4*i4+3
    const int j8   = t7 & 7;            // 0..7 : cols/keys 8*j8 .. 8*j8+7
    const int n0   = blockIdx.x * TQ;

    // swizzled quad offsets for this thread's two 16B quads (quads 2j8, 2j8+1)
    const int qa = 2 * j8, qb = 2 * j8 + 1;
    const int offA = 4 * (qa ^ (qa >> 3));
    const int offB = 4 * (qb ^ (qb >> 3));

    // stage Qtd (duplicated): Qtd[d][2r,2r+1] = adj[n0+r][d]
#pragma unroll
    for (int t = 0; t < 2; t++) {
        int idx = tid + 512 * t;
        int r = idx >> 4, d = idx & 15;
        float v = adj[(n0 + r) * EMB + d];
        *(float2*)&Qtd[d * 132 + 2 * r] = make_float2(v, v);
    }

    const float* ktp  = Kt + half * 1088;
    const float* vsp  = Vs + half * 4096;
    float*       ptw  = Pt + half * 4480;
    const float* ptr_ = Pt + half * 4480 + 4 * i4;
    const float* qtp  = Qtd + 8 * i4;

    u64 a01[8], a23[8];
#pragma unroll
    for (int c = 0; c < 8; c++) { a01[c] = 0; a23[c] = 0; }
    float l0 = 0.f, l1 = 0.f, l2 = 0.f, l3 = 0.f;

    const int sd = tid & 15, skr = tid >> 4;   // K staging ids

    for (int kt = 0; kt < NN; kt += KITER) {
        __syncthreads();   // prev PV done: Kt/Vs safe to overwrite
        // ---- stage K (transposed, quad-swizzled): Kt[h][d][k] ----
#pragma unroll
        for (int m = 0; m < 8; m++) {
            int g = skr + 32 * m;                  // global key 0..255
            float v = adj[(kt + g) * EMB + sd];
            int h = g >> 6, k = g & 63;
            int q = k >> 2, p = k & 3;
            Kt[h * 1088 + sd * 68 + 4 * (q ^ (q >> 3)) + p] = v;
        }
        // ---- stage V (quad-swizzled rows) ----
#pragma unroll
        for (int t = 0; t < 8; t++) {
            int idx = tid + 512 * t;               // 0..4095
            int row = idx >> 4, q = idx & 15;
            float4 v = *(const float4*)(g_Xt + (size_t)(kt + row) * 64 + 4 * q);
            *(float4*)&Vs[(row >> 6) * 4096 + (row & 63) * 64 + 4 * (q ^ (q >> 3))] = v;
        }
        __syncthreads();

        // ---- scores: s[r][kp] = pair of scores (row r) x (keys 8j8+2kp, +2kp+1) ----
        u64 s[16];
#pragma unroll
        for (int t = 0; t < 16; t++) s[t] = 0;
#pragma unroll
        for (int d = 0; d < EMB; d++) {
            const float* kd_ = ktp + d * 68;
            ulonglong2 kA = *(const ulonglong2*)(kd_ + offA);   // key-pairs (0,1),(2,3)
            ulonglong2 kB = *(const ulonglong2*)(kd_ + offB);   // key-pairs (4,5),(6,7)
            const float* qd_ = qtp + d * 132;
            ulonglong2 qA = *(const ulonglong2*)(qd_);          // dup(r0), dup(r1)
            ulonglong2 qB = *(const ulonglong2*)(qd_ + 4);      // dup(r2), dup(r3)
            s[0]  = ffma2(qA.x, kA.x, s[0]);  s[1]  = ffma2(qA.x, kA.y, s[1]);
            s[2]  = ffma2(qA.x, kB.x, s[2]);  s[3]  = ffma2(qA.x, kB.y, s[3]);
            s[4]  = ffma2(qA.y, kA.x, s[4]);  s[5]  = ffma2(qA.y, kA.y, s[5]);
            s[6]  = ffma2(qA.y, kB.x, s[6]);  s[7]  = ffma2(qA.y, kB.y, s[7]);
            s[8]  = ffma2(qB.x, kA.x, s[8]);  s[9]  = ffma2(qB.x, kA.y, s[9]);
            s[10] = ffma2(qB.x, kB.x, s[10]); s[11] = ffma2(qB.x, kB.y, s[11]);
            s[12] = ffma2(qB.y, kA.x, s[12]); s[13] = ffma2(qB.y, kA.y, s[13]);
            s[14] = ffma2(qB.y, kB.x, s[14]); s[15] = ffma2(qB.y, kB.y, s[15]);
        }
        // ---- exp(relu(s)), partial row sums, transposed P store ----
        float pr[4][8];
#pragma unroll
        for (int r = 0; r < 4; r++)
#pragma unroll
            for (int kp = 0; kp < 4; kp++) {
                float2 u = unpk(s[r * 4 + kp]);
                pr[r][2 * kp]     = __expf(fminf(fmaxf(u.x, 0.f), 70.f));
                pr[r][2 * kp + 1] = __expf(fminf(fmaxf(u.y, 0.f), 70.f));
            }
#pragma unroll
        for (int c = 0; c < 8; c++) {
            l0 += pr[0][c]; l1 += pr[1][c]; l2 += pr[2][c]; l3 += pr[3][c];
            float* wptr = ptw + (8 * j8 + c) * 70 + 4 * i4;
            *(float2*)wptr       = make_float2(pr[0][c], pr[1][c]);
            *(float2*)(wptr + 2) = make_float2(pr[2][c], pr[3][c]);
        }
        __syncthreads();   // P ready

        // ---- PV: a[row-pair][col] += (p_r,p_r') * dup(v_col) ----
#pragma unroll 4
        for (int kk = 0; kk < KS; kk++) {
            u64 p01 = *(const u64*)(ptr_ + kk * 70);
            u64 p23 = *(const u64*)(ptr_ + kk * 70 + 2);
            const float* vk = vsp + kk * 64;
            ulonglong2 vA = *(const ulonglong2*)(vk + offA);   // cols 8j8..+3
            ulonglong2 vB = *(const ulonglong2*)(vk + offB);   // cols 8j8+4..+7
            float2 fa = unpk(vA.x), fb = unpk(vA.y), fc = unpk(vB.x), fd = unpk(vB.y);
            u64 d0 = pk2(fa.x), d1 = pk2(fa.y), d2 = pk2(fb.x), d3 = pk2(fb.y);
            u64 d4 = pk2(fc.x), d5 = pk2(fc.y), d6 = pk2(fd.x), d7 = pk2(fd.y);
            a01[0] = ffma2(p01, d0, a01[0]);  a23[0] = ffma2(p23, d0, a23[0]);
            a01[1] = ffma2(p01, d1, a01[1]);  a23[1] = ffma2(p23, d1, a23[1]);
            a01[2] = ffma2(p01, d2, a01[2]);  a23[2] = ffma2(p23, d2, a23[2]);
            a01[3] = ffma2(p01, d3, a01[3]);  a23[3] = ffma2(p23, d3, a23[3]);
            a01[4] = ffma2(p01, d4, a01[4]);  a23[4] = ffma2(p23, d4, a23[4]);
            a01[5] = ffma2(p01, d5, a01[5]);  a23[5] = ffma2(p23, d5, a23[5]);
            a01[6] = ffma2(p01, d6, a01[6]);  a23[6] = ffma2(p23, d6, a23[6]);
            a01[7] = ffma2(p01, d7, a01[7]);  a23[7] = ffma2(p23, d7, a23[7]);
        }
    }
    __syncthreads();   // S1: all PV (reads of Pt/Vs) done

    // row-sum reduce over j8 (lane bits 0..2), store per (half, row)
    l0 += __shfl_xor_sync(0xffffffffu, l0, 1);
    l0 += __shfl_xor_sync(0xffffffffu, l0, 2);
    l0 += __shfl_xor_sync(0xffffffffu, l0, 4);
    l1 += __shfl_xor_sync(0xffffffffu, l1, 1);
    l1 += __shfl_xor_sync(0xffffffffu, l1, 2);
    l1 += __shfl_xor_sync(0xffffffffu, l1, 4);
    l2 += __shfl_xor_sync(0xffffffffu, l2, 1);
    l2 += __shfl_xor_sync(0xffffffffu, l2, 2);
    l2 += __shfl_xor_sync(0xffffffffu, l2, 4);
    l3 += __shfl_xor_sync(0xffffffffu, l3, 1);
    l3 += __shfl_xor_sync(0xffffffffu, l3, 2);
    l3 += __shfl_xor_sync(0xffffffffu, l3, 4);
    if ((tid & 7) == 0)
        *(float4*)&lred[half * 64 + 4 * i4] = make_float4(l0, l1, l2, l3);

    // halves 1..3 stage their partial accumulators (Pt region overlay)
    if (half != 0) {
        float* st = smf + OFF_ACC + (size_t)((half - 1) * 128 + t7) * 32;
#pragma unroll
        for (int c = 0; c < 8; c++) {
            *(u64*)(st + 4 * c)      = a01[c];
            *(u64*)(st + 4 * c + 2)  = a23[c];
        }
    }
    // stage pools into Vs overlay
    float* wpsm = smf + OFF_WPS;
    float* bpsm = smf + OFF_BPS;
    ((float4*)wpsm)[tid]       = ((const float4*)wp)[tid];
    ((float4*)wpsm)[tid + 512] = ((const float4*)wp)[tid + 512];
    if (tid < 256) ((float4*)bpsm)[tid] = ((const float4*)bp)[tid];
    __syncthreads();   // S2

    float* Ysm = smf + OFF_YS;
    if (half == 0) {
        // merge 4 partials
#pragma unroll
        for (int h = 0; h < 3; h++) {
            const float* st = smf + OFF_ACC + (size_t)(h * 128 + t7) * 32;
#pragma unroll
            for (int c = 0; c < 8; c++) {
                a01[c] = add2(a01[c], *(const u64*)(st + 4 * c));
                a23[c] = add2(a23[c], *(const u64*)(st + 4 * c + 2));
            }
        }
        // denominators
        float4 La = *(const float4*)&lred[4 * i4];
        float4 Lb = *(const float4*)&lred[64 + 4 * i4];
        float4 Lc = *(const float4*)&lred[128 + 4 * i4];
        float4 Ld = *(const float4*)&lred[192 + 4 * i4];
        float inv0 = 1.f / (La.x + Lb.x + Lc.x + Ld.x);
        float inv1 = 1.f / (La.y + Lb.y + Lc.y + Ld.y);
        float inv2 = 1.f / (La.z + Lb.z + Lc.z + Ld.z);
        float inv3 = 1.f / (La.w + Lb.w + Lc.w + Ld.w);
        // normalize + write y tile (natural col order, pitch 68)
        float y0[8], y1[8], y2[8], y3[8];
#pragma unroll
        for (int c = 0; c < 8; c++) {
            float2 u = unpk(a01[c]); float2 w = unpk(a23[c]);
            y0[c] = u.x * inv0; y1[c] = u.y * inv1;
            y2[c] = w.x * inv2; y3[c] = w.y * inv3;
        }
        int rbase = 4 * i4;
        *(float4*)&Ysm[(rbase + 0) * 68 + 8 * j8]     = *(float4*)&y0[0];
        *(float4*)&Ysm[(rbase + 0) * 68 + 8 * j8 + 4] = *(float4*)&y0[4];
        *(float4*)&Ysm[(rbase + 1) * 68 + 8 * j8]     = *(float4*)&y1[0];
        *(float4*)&Ysm[(rbase + 1) * 68 + 8 * j8 + 4] = *(float4*)&y1[4];
        *(float4*)&Ysm[(rbase + 2) * 68 + 8 * j8]     = *(float4*)&y2[0];
        *(float4*)&Ysm[(rbase + 2) * 68 + 8 * j8 + 4] = *(float4*)&y2[4];
        *(float4*)&Ysm[(rbase + 3) * 68 + 8 * j8]     = *(float4*)&y3[0];
        *(float4*)&Ysm[(rbase + 3) * 68 + 8 * j8 + 4] = *(float4*)&y3[4];
    }
    __syncthreads();   // S3

    // ---- epilogue: out[b,n,o] = bias + x·W0 + y·W1 ----
    const int o  = tid & 63;
    const int ng = tid >> 6;   // 0..7, 8 rows each
#pragma unroll
    for (int q = 0; q < 8; q++) {
        int n = ng * 8 + q;
        float w00 = 0.f, w01 = 0.f, w10 = 0.f, w11 = 0.f, bbv = 0.f;
#pragma unroll
        for (int d = 0; d < EMB; d++) {
            float a = Qtd[d * 132 + 2 * n];
            const float* wrow = wpsm + d * 256 + o;   // (d*4 + 2k + i)*64 + o
            w00 += a * wrow[0];
            w01 += a * wrow[64];
            w10 += a * wrow[128];
            w11 += a * wrow[192];
            bbv += a * bpsm[d * 64 + o];
        }
        int gn = n0 + n;
        const float* xrow = g_Xt + (size_t)gn * 64;
        const float* yrow = Ysm + n * 68;
        float* orow = out + (size_t)gn * 64 + o;
#pragma unroll 4
        for (int b = 0; b < BB; b++) {
            float2 xv = *(const float2*)(xrow + 2 * b);
            float2 yv = *(const float2*)(yrow + 2 * b);
            orow[(size_t)b * (NN * 64)] = bbv + xv.x * w00 + xv.y * w01 + yv.x * w10 + yv.y * w11;
        }
    }
}

extern "C" void kernel_launch(void* const* d_in, const int* in_sizes, int n_in,
                              void* d_out, int out_size) {
    const float* x   = (const float*)d_in[0];   // [32, 8192, 2]
    const float* adj = (const float*)d_in[1];   // [8192, 16]
    const float* wp  = (const float*)d_in[2];   // [16, 2, 2, 64]
    const float* bp  = (const float*)d_in[3];   // [16, 64]
    float* out = (float*)d_out;                 // [32, 8192, 64]

    cudaFuncSetAttribute(gconv_attn_kernel,
                         cudaFuncAttributeMaxDynamicSharedMemorySize,
                         SMEM_FLOATS * (int)sizeof(float));
    transpose_x_kernel<<<NN / 256, 256>>>(x);
    gconv_attn_kernel<<<NN / TQ, 512, SMEM_FLOATS * sizeof(float)>>>(adj, wp, bp, out);
}